// round 14
// baseline (speedup 1.0000x reference)
#include <cuda_runtime.h>

// Problem constants (fixed by the reference)
#define N_SAE  128
#define D_DATA 128
#define D_DICT 512
#define BATCH  1024
#define TB     32     // tokens per MMA batch
#define TCAP   48     // max tokens per expert (mean 16; 8-sigma margin)
#define NTHR   1024   // 32 warps

typedef unsigned long long u64;
typedef unsigned int u32;

// Cross-CTA combine state (MONOTONIC across graph replays; never reset).
__device__ float g_stage[BATCH * D_DATA];
__device__ int   g_arr  [BATCH];
__device__ int   g_ready[BATCH];

// ---------------- helpers ----------------
__device__ __forceinline__ u64 pk(float lo, float hi) {
    u64 r; asm("mov.b64 %0,{%1,%2};" : "=l"(r) : "f"(lo), "f"(hi)); return r;
}
__device__ __forceinline__ void upk(float& lo, float& hi, u64 v) {
    asm("mov.b64 {%0,%1},%2;" : "=f"(lo), "=f"(hi) : "l"(v));
}
__device__ __forceinline__ u64 add2(u64 a, u64 b) {
    u64 d; asm("add.rn.f32x2 %0,%1,%2;" : "=l"(d) : "l"(a), "l"(b)); return d;
}
__device__ __forceinline__ u32 tf32r(float f) {   // unbiased round-to-nearest tf32
    u32 r; asm("cvt.rna.tf32.f32 %0,%1;" : "=r"(r) : "f"(f)); return r;
}
__device__ __forceinline__ void mma_tf32(float& c0, float& c1, float& c2, float& c3,
                                         u32 a0, u32 a1, u32 a2, u32 a3,
                                         u32 b0, u32 b1) {
    asm("mma.sync.aligned.m16n8k8.row.col.f32.tf32.tf32.f32 "
        "{%0,%1,%2,%3},{%4,%5,%6,%7},{%8,%9},{%0,%1,%2,%3};"
        : "+f"(c0), "+f"(c1), "+f"(c2), "+f"(c3)
        : "r"(a0), "r"(a1), "r"(a2), "r"(a3), "r"(b0), "r"(b1));
}

// Dynamic smem (floats). xs[128][40], acts[512][40], part u64[4][16][128].
// Row pad 40: LDS bank = (8t+g) mod 32 for B fragments -> conflict-free.
#define XROW 40
#define OFF_XS   0
#define OFF_ACTS (OFF_XS + D_DATA * XROW)        // 5120
#define OFF_PART (OFF_ACTS + D_DICT * XROW)      // 25600 (u64 region: 8192 u64)
#define SMEM_FLOATS (OFF_PART + 8192 * 2)
#define SMEM_BYTES (SMEM_FLOATS * 4)             // 167936 B (1 CTA/SM)

// ---------------------------------------------------------------------------
// One CTA per expert, grid = 128, 1024 threads (32 warps, 8/SMSP).
// Doubled warp count halves per-warp serial work -> hides the LDG/LDS/MMA
// dependency latency that bound the 16-warp version.
// ---------------------------------------------------------------------------
__global__ void __launch_bounds__(NTHR, 1)
k_compute(const float* __restrict__ x,
          const float* __restrict__ gate,
          const float* __restrict__ Wenc,
          const float* __restrict__ Wdec,
          const float* __restrict__ benc,
          const float* __restrict__ bdec,
          float* __restrict__ out) {
    int s = blockIdx.x;

    extern __shared__ __align__(16) float smf[];
    float* xs   = smf + OFF_XS;
    float* acts = smf + OFF_ACTS;
    u64*   part = (u64*)(smf + OFF_PART);

    __shared__ float gsf[64];
    __shared__ int prtok[64];
    __shared__ int pj[64];
    __shared__ int sarr[TB];
    __shared__ unsigned masks[32];
    __shared__ int pcnt[32];
    __shared__ int ntot;

    int tid  = threadIdx.x;
    int warp = tid >> 5, lane = tid & 31;
    int g = lane >> 2, t = lane & 3;       // mma fragment coords

    const float* WencS = Wenc + (size_t)s * D_DATA * D_DICT;
    const float* WdecS = Wdec + (size_t)s * D_DICT * D_DATA;

    // ---- Routing: column scan of gate[:, s] (one token per thread) ----
    float v0 = __ldg(&gate[(size_t)tid * N_SAE + s]);
    unsigned m0 = __ballot_sync(0xffffffffu, v0 != 0.0f);
    if (lane == 0) masks[warp] = m0;
    if (tid < 64) { prtok[tid] = 0; gsf[tid] = 0.0f; pj[tid] = 0; }
    __syncthreads();
    if (warp == 0) {
        int c = __popc(masks[lane]);
        int ex = c;
        #pragma unroll
        for (int o = 1; o < 32; o <<= 1) {
            int tt = __shfl_up_sync(0xffffffffu, ex, o);
            if (lane >= o) ex += tt;
        }
        pcnt[lane] = ex - c;
        if (lane == 31) ntot = ex;
    }
    __syncthreads();
    int n = ntot; if (n > TCAP) n = TCAP;
    if (n == 0) return;

    if (v0 != 0.0f) {
        int r = pcnt[warp] + __popc(m0 & ((1u << lane) - 1));
        if (r < TCAP) { prtok[r] = tid; gsf[r] = v0; }
    }
    __syncthreads();

    // ---- Slot j per token (pair id): warp row-scans gate[token] ----
    for (int tk = warp; tk < n; tk += 32) {
        int b = prtok[tk];
        float4 gv = ((const float4*)gate)[(size_t)b * (N_SAE / 4) + lane];
        int e0 = lane * 4;
        int c = (gv.x != 0.0f && e0     < s) + (gv.y != 0.0f && e0 + 1 < s)
              + (gv.z != 0.0f && e0 + 2 < s) + (gv.w != 0.0f && e0 + 3 < s);
        #pragma unroll
        for (int o = 16; o > 0; o >>= 1) c += __shfl_xor_sync(0xffffffffu, c, o);
        if (lane == 0) pj[tk] = b * 2 + c;
    }

    // ================= Batch loop (usually one iteration) =================
    for (int base = 0; base < n; base += TB) {
        int mb = n - base; if (mb > TB) mb = TB;

        // ---- xs[d][slot], tf32-rounded; pad slots -> 0 ----
        for (int i = tid; i < D_DATA * TB; i += NTHR) {
            int j = i & 31, d = i >> 5;
            float v = (j < mb) ? x[(size_t)prtok[base + j] * D_DATA + d] : 0.0f;
            xs[d * XROW + j] = __uint_as_float(tf32r(v));
        }
        __syncthreads();

        // ---------------- Encode: C[512e x 32tok], warp = one m16 e-tile ----
        {
            int e0 = warp * 16;
            const float* pa = WencS + t * D_DICT + e0 + g;
            float c[4][4];
            #pragma unroll
            for (int nt = 0; nt < 4; nt++)
                #pragma unroll
                for (int q = 0; q < 4; q++) c[nt][q] = 0.0f;

            #pragma unroll 4
            for (int ks = 0; ks < 16; ks++) {
                u32 a0 = tf32r(pa[0]);
                u32 a1 = tf32r(pa[8]);
                u32 a2 = tf32r(pa[4 * D_DICT]);
                u32 a3 = tf32r(pa[4 * D_DICT + 8]);
                #pragma unroll
                for (int nt = 0; nt < 4; nt++) {
                    u32 b0 = __float_as_uint(xs[(8 * ks + t    ) * XROW + nt * 8 + g]);
                    u32 b1 = __float_as_uint(xs[(8 * ks + t + 4) * XROW + nt * 8 + g]);
                    mma_tf32(c[nt][0], c[nt][1], c[nt][2], c[nt][3],
                             a0, a1, a2, a3, b0, b1);
                }
                pa += 8 * D_DICT;
            }

            // bias + relu + gate + tf32-round -> acts[e][slot]
            int e = e0 + g;
            float bg  = benc[(size_t)s * D_DICT + e];
            float bg8 = benc[(size_t)s * D_DICT + e + 8];
            #pragma unroll
            for (int nt = 0; nt < 4; nt++) {
                int sl = nt * 8 + 2 * t;
                float gt0 = gsf[base + sl], gt1 = gsf[base + sl + 1];
                acts[(e    ) * XROW + sl    ] = __uint_as_float(tf32r(fmaxf(c[nt][0] + bg , 0.f) * gt0));
                acts[(e    ) * XROW + sl + 1] = __uint_as_float(tf32r(fmaxf(c[nt][1] + bg , 0.f) * gt1));
                acts[(e + 8) * XROW + sl    ] = __uint_as_float(tf32r(fmaxf(c[nt][2] + bg8, 0.f) * gt0));
                acts[(e + 8) * XROW + sl + 1] = __uint_as_float(tf32r(fmaxf(c[nt][3] + bg8, 0.f) * gt1));
            }
        }
        __syncthreads();

        // ---------------- Decode: C[128d x 32tok], warp = d-tile x K-quarter ----
        {
            int d0 = (warp & 7) * 16;
            int qk = warp >> 3;            // K-quarter: e in [128qk, 128qk+128)
            const float* pa = WdecS + (size_t)(qk * 128 + t) * D_DATA + d0 + g;
            float c[4][4];
            #pragma unroll
            for (int nt = 0; nt < 4; nt++)
                #pragma unroll
                for (int q = 0; q < 4; q++) c[nt][q] = 0.0f;

            #pragma unroll 4
            for (int ks = 0; ks < 16; ks++) {
                u32 a0 = tf32r(pa[0]);
                u32 a1 = tf32r(pa[8]);
                u32 a2 = tf32r(pa[4 * D_DATA]);
                u32 a3 = tf32r(pa[4 * D_DATA + 8]);
                #pragma unroll
                for (int nt = 0; nt < 4; nt++) {
                    u32 b0 = __float_as_uint(acts[(qk * 128 + 8 * ks + t    ) * XROW + nt * 8 + g]);
                    u32 b1 = __float_as_uint(acts[(qk * 128 + 8 * ks + t + 4) * XROW + nt * 8 + g]);
                    mma_tf32(c[nt][0], c[nt][1], c[nt][2], c[nt][3],
                             a0, a1, a2, a3, b0, b1);
                }
                pa += 8 * D_DATA;
            }
            // part[quarter][token-pair nt*4+t][d] = pk(tok even, tok odd)
            #pragma unroll
            for (int nt = 0; nt < 4; nt++) {
                part[qk * 2048 + (nt * 4 + t) * 128 + d0 + g    ] = pk(c[nt][0], c[nt][1]);
                part[qk * 2048 + (nt * 4 + t) * 128 + d0 + g + 8] = pk(c[nt][2], c[nt][3]);
            }
        }
        __syncthreads();

        // ---- Epilogue: reduce 4 K-quarters + b_dec, lock-free combine ----
        {
            int d  = tid & 127;
            int tl = tid >> 7;             // 0..7; token pairs tl, tl+8
            float bd = bdec[(size_t)s * D_DATA + d];
            float vv[4];
            #pragma unroll
            for (int q = 0; q < 2; q++) {
                int tp = tl + 8 * q;
                u64 sum = add2(add2(part[           tp * 128 + d],
                                    part[1 * 2048 + tp * 128 + d]),
                               add2(part[2 * 2048 + tp * 128 + d],
                                    part[3 * 2048 + tp * 128 + d]));
                float lo, hi; upk(lo, hi, sum);
                vv[2 * q] = lo + bd; vv[2 * q + 1] = hi + bd;
            }

            if (tid < TB) sarr[tid] = (tid < mb) ? atomicAdd(&g_arr[prtok[base + tid]], 1) : 0;
            __syncthreads();

            // Phase 1: publish first-role rows (parity 0).
            #pragma unroll
            for (int q = 0; q < 2; q++) {
                #pragma unroll
                for (int r = 0; r < 2; r++) {
                    int j = 2 * (tl + 8 * q) + r;
                    if (j < mb && (sarr[j] & 1) == 0)
                        __stcg(&g_stage[(size_t)prtok[base + j] * D_DATA + d], vv[2 * q + r]);
                }
            }
            __syncthreads();

            if (tid < mb && (sarr[tid] & 1) == 0) {
                __threadfence();
                atomicAdd(&g_ready[prtok[base + tid]], 1);
            }
            // Phase 2: spin (publish-before-spin => no deadlock).
            if (tid < mb && (sarr[tid] & 1) == 1) {
                int b = prtok[base + tid];
                int want = (sarr[tid] >> 1) + 1;
                while (atomicAdd(&g_ready[b], 0) < want) {}
                __threadfence();
            }
            __syncthreads();

            // Phase 3: combine and write final output (second-role tokens).
            #pragma unroll
            for (int q = 0; q < 2; q++) {
                #pragma unroll
                for (int r = 0; r < 2; r++) {
                    int j = 2 * (tl + 8 * q) + r;
                    if (j < mb && (sarr[j] & 1) == 1) {
                        int b = prtok[base + j];
                        float other = __ldcg(&g_stage[(size_t)b * D_DATA + d]);
                        out[(size_t)b * D_DATA + d] = vv[2 * q + r] + other;
                    }
                }
            }
        }
        __syncthreads();   // before next batch reuses xs/acts/part
    }
}

// ---------------------------------------------------------------------------
// Launch. Inputs (metadata order): x, gate, W_enc, W_dec, b_enc, b_dec, k
// ---------------------------------------------------------------------------
extern "C" void kernel_launch(void* const* d_in, const int* in_sizes, int n_in,
                              void* d_out, int out_size) {
    const float* x    = (const float*)d_in[0];
    const float* gate = (const float*)d_in[1];
    const float* Wenc = (const float*)d_in[2];
    const float* Wdec = (const float*)d_in[3];
    const float* benc = (const float*)d_in[4];
    const float* bdec = (const float*)d_in[5];
    float* out = (float*)d_out;

    cudaFuncSetAttribute(k_compute, cudaFuncAttributeMaxDynamicSharedMemorySize,
                         SMEM_BYTES);

    k_compute<<<N_SAE, NTHR, SMEM_BYTES>>>(x, gate, Wenc, Wdec, benc, bdec, out);
}

// round 15
// speedup vs baseline: 1.0690x; 1.0690x over previous
#include <cuda_runtime.h>

// Problem constants (fixed by the reference)
#define N_SAE  128
#define D_DATA 128
#define D_DICT 512
#define BATCH  1024
#define TB     32     // tokens per MMA batch
#define TCAP   48     // max tokens per expert (mean 16; 8-sigma margin)

typedef unsigned long long u64;
typedef unsigned int u32;

// Cross-CTA combine state (MONOTONIC across graph replays; never reset).
__device__ float g_stage[BATCH * D_DATA];
__device__ int   g_arr  [BATCH];
__device__ int   g_ready[BATCH];

// ---------------- helpers ----------------
__device__ __forceinline__ u64 pk(float lo, float hi) {
    u64 r; asm("mov.b64 %0,{%1,%2};" : "=l"(r) : "f"(lo), "f"(hi)); return r;
}
__device__ __forceinline__ void upk(float& lo, float& hi, u64 v) {
    asm("mov.b64 {%0,%1},%2;" : "=f"(lo), "=f"(hi) : "l"(v));
}
__device__ __forceinline__ u64 add2(u64 a, u64 b) {
    u64 d; asm("add.rn.f32x2 %0,%1,%2;" : "=l"(d) : "l"(a), "l"(b)); return d;
}
__device__ __forceinline__ u32 tf32r(float f) {   // unbiased round-to-nearest tf32
    u32 r; asm("cvt.rna.tf32.f32 %0,%1;" : "=r"(r) : "f"(f)); return r;
}
__device__ __forceinline__ u32 tf32s(float f) {   // tf32 round of a smem float
    u32 r; asm("cvt.rna.tf32.f32 %0,%1;" : "=r"(r) : "f"(f)); return r;
}
__device__ __forceinline__ void mma_tf32(float& c0, float& c1, float& c2, float& c3,
                                         u32 a0, u32 a1, u32 a2, u32 a3,
                                         u32 b0, u32 b1) {
    asm("mma.sync.aligned.m16n8k8.row.col.f32.tf32.tf32.f32 "
        "{%0,%1,%2,%3},{%4,%5,%6,%7},{%8,%9},{%0,%1,%2,%3};"
        : "+f"(c0), "+f"(c1), "+f"(c2), "+f"(c3)
        : "r"(a0), "r"(a1), "r"(a2), "r"(a3), "r"(b0), "r"(b1));
}
__device__ __forceinline__ u32 smem_u32(const void* p) {
    u32 a;
    asm("{.reg .u64 t; cvta.to.shared.u64 t,%1; cvt.u32.u64 %0,t;}" : "=r"(a) : "l"(p));
    return a;
}
#define CP16(dst, src) \
    asm volatile("cp.async.ca.shared.global [%0],[%1],16;" :: "r"(dst), "l"(src))
#define CP_COMMIT() asm volatile("cp.async.commit_group;" ::: "memory")
#define CP_WAIT2()  asm volatile("cp.async.wait_group 2;" ::: "memory")

// Dynamic smem (floats).
//  wstg : 16 warps x 4 stages x 8 rows x 40 floats  (per-warp private rings;
//         decode reuses the same region with 8 x 24 slots)          81920 B
//  xs   : [128][40]  (TB=32 tokens used; pad 40 -> bank (8t+g))     20480 B
//  acts : [512][40]                                                 81920 B
//  part : u64[2][16][128]                                           32768 B
#define WREG  (4 * 8 * 40)                   // 1280 floats per warp
#define OFF_WSTG 0
#define OFF_XS   (16 * WREG)                 // 20480
#define OFF_ACTS (OFF_XS + D_DATA * 40)      // 25600
#define OFF_PART (OFF_ACTS + D_DICT * 40)    // 46080
#define SMEM_FLOATS (OFF_PART + 4096 * 2)    // 54272
#define SMEM_BYTES  (SMEM_FLOATS * 4)        // 217088 B (1 CTA/SM)

// ---------------------------------------------------------------------------
// One CTA per expert, grid = 128, 512 threads (16 warps).
// Weights flow through per-warp PRIVATE cp.async rings (depth 4, wait_group 2,
// __syncwarp only -- no CTA barriers in the mainloops). Fragments read from
// smem with conflict-free banks; MMA core / routing / combine = proven R12.
// ---------------------------------------------------------------------------
__global__ void __launch_bounds__(512, 1)
k_compute(const float* __restrict__ x,
          const float* __restrict__ gate,
          const float* __restrict__ Wenc,
          const float* __restrict__ Wdec,
          const float* __restrict__ benc,
          const float* __restrict__ bdec,
          float* __restrict__ out) {
    int s = blockIdx.x;

    extern __shared__ __align__(16) float smf[];
    float* xs   = smf + OFF_XS;
    float* acts = smf + OFF_ACTS;
    u64*   part = (u64*)(smf + OFF_PART);

    __shared__ float gsf[64];
    __shared__ int prtok[64];
    __shared__ int pj[64];
    __shared__ int sarr[TB];
    __shared__ unsigned masks[32];
    __shared__ int pcnt[32];
    __shared__ int ntot;

    int tid  = threadIdx.x;
    int warp = tid >> 5, lane = tid & 31;
    int g = lane >> 2, t = lane & 3;       // mma fragment coords

    float* wreg = smf + OFF_WSTG + warp * WREG;   // this warp's private ring
    u32 wregu = smem_u32(wreg);

    const float* WencS = Wenc + (size_t)s * D_DATA * D_DICT;
    const float* WdecS = Wdec + (size_t)s * D_DICT * D_DATA;

    // ---- Routing: column scan of gate[:, s] (proven) ----
    float v0 = __ldg(&gate[(size_t)tid * N_SAE + s]);
    float v1 = __ldg(&gate[(size_t)(tid + 512) * N_SAE + s]);
    unsigned m0 = __ballot_sync(0xffffffffu, v0 != 0.0f);
    unsigned m1 = __ballot_sync(0xffffffffu, v1 != 0.0f);
    if (lane == 0) { masks[warp] = m0; masks[16 + warp] = m1; }
    if (tid < 64) { prtok[tid] = 0; gsf[tid] = 0.0f; pj[tid] = 0; }
    __syncthreads();
    if (warp == 0) {
        int c = __popc(masks[lane]);
        int ex = c;
        #pragma unroll
        for (int o = 1; o < 32; o <<= 1) {
            int tt = __shfl_up_sync(0xffffffffu, ex, o);
            if (lane >= o) ex += tt;
        }
        pcnt[lane] = ex - c;
        if (lane == 31) ntot = ex;
    }
    __syncthreads();
    int n = ntot; if (n > TCAP) n = TCAP;
    if (n == 0) return;

    if (v0 != 0.0f) {
        int r = pcnt[warp] + __popc(m0 & ((1u << lane) - 1));
        if (r < TCAP) { prtok[r] = tid; gsf[r] = v0; }
    }
    if (v1 != 0.0f) {
        int r = pcnt[16 + warp] + __popc(m1 & ((1u << lane) - 1));
        if (r < TCAP) { prtok[r] = tid + 512; gsf[r] = v1; }
    }
    __syncthreads();

    // ---- Slot j per token (pair id): warp row-scans gate[token] ----
    for (int tk = warp; tk < n; tk += 16) {
        int b = prtok[tk];
        float4 gv = ((const float4*)gate)[(size_t)b * (N_SAE / 4) + lane];
        int e0 = lane * 4;
        int c = (gv.x != 0.0f && e0     < s) + (gv.y != 0.0f && e0 + 1 < s)
              + (gv.z != 0.0f && e0 + 2 < s) + (gv.w != 0.0f && e0 + 3 < s);
        #pragma unroll
        for (int o = 16; o > 0; o >>= 1) c += __shfl_xor_sync(0xffffffffu, c, o);
        if (lane == 0) pj[tk] = b * 2 + c;
    }

    // Encode stager role: lane covers row (lane>>3) and (lane>>3)+4,
    // 16B chunk (lane&7) of the warp's 32-float e-band.
    int er = lane >> 3, ec = lane & 7;
    // Decode stager role: lane covers row (lane>>2), 16B chunk (lane&3).
    int dr = lane >> 2, dc = lane & 3;

    // ================= Batch loop (usually one iteration) =================
    for (int base = 0; base < n; base += TB) {
        int mb = n - base; if (mb > TB) mb = TB;

        int e0 = warp * 32;                     // encode e-band
        // ---- Encode prologue: stage slices 0..2 into the private ring ----
        #pragma unroll
        for (int p = 0; p < 3; p++) {
            const float* src = WencS + (size_t)(8 * p + er) * D_DICT + e0 + ec * 4;
            u32 dst = wregu + (p * 320 + er * 40 + ec * 4) * 4;
            CP16(dst, src);
            CP16(dst + 4 * 40 * 4, src + 4 * D_DICT);
            CP_COMMIT();
        }

        // ---- xs[d][slot], tf32-rounded (overlaps prefetch) ----
        for (int i = tid; i < D_DATA * TB; i += 512) {
            int j = i & 31, d = i >> 5;
            float v = (j < mb) ? x[(size_t)prtok[base + j] * D_DATA + d] : 0.0f;
            xs[d * 40 + j] = __uint_as_float(tf32r(v));
        }
        __syncthreads();                        // xs visible

        // ---------------- Encode: C[512e x 32tok] ----------------
        float c0[4][4], c1[4][4];
        #pragma unroll
        for (int nt = 0; nt < 4; nt++)
            #pragma unroll
            for (int q = 0; q < 4; q++) { c0[nt][q] = 0.0f; c1[nt][q] = 0.0f; }

        #pragma unroll 4
        for (int ks = 0; ks < 16; ks++) {
            CP_WAIT2();
            if (ks + 3 < 16) {
                int p = ks + 3;
                const float* src = WencS + (size_t)(8 * p + er) * D_DICT + e0 + ec * 4;
                u32 dst = wregu + (((p & 3) * 320 + er * 40 + ec * 4)) * 4;
                CP16(dst, src);
                CP16(dst + 4 * 40 * 4, src + 4 * D_DICT);
            }
            CP_COMMIT();                        // empty group at tail keeps counts exact
            __syncwarp();

            const float* S = wreg + (ks & 3) * 320;
            u32 a00 = tf32s(S[t * 40 + g     ]);
            u32 a01 = tf32s(S[t * 40 + g +  8]);
            u32 a02 = tf32s(S[(t + 4) * 40 + g     ]);
            u32 a03 = tf32s(S[(t + 4) * 40 + g +  8]);
            u32 a10 = tf32s(S[t * 40 + g + 16]);
            u32 a11 = tf32s(S[t * 40 + g + 24]);
            u32 a12 = tf32s(S[(t + 4) * 40 + g + 16]);
            u32 a13 = tf32s(S[(t + 4) * 40 + g + 24]);
            #pragma unroll
            for (int nt = 0; nt < 4; nt++) {
                u32 b0 = __float_as_uint(xs[(8 * ks + t    ) * 40 + nt * 8 + g]);
                u32 b1 = __float_as_uint(xs[(8 * ks + t + 4) * 40 + nt * 8 + g]);
                mma_tf32(c0[nt][0], c0[nt][1], c0[nt][2], c0[nt][3],
                         a00, a01, a02, a03, b0, b1);
                mma_tf32(c1[nt][0], c1[nt][1], c1[nt][2], c1[nt][3],
                         a10, a11, a12, a13, b0, b1);
            }
        }

        // ---- Decode prologue: stage slices 0..2 (ring reuse is safe: this
        //      warp's encode reads are complete in program order) ----
        int d0 = (warp & 7) * 16;
        int half = warp >> 3;
        #pragma unroll
        for (int p = 0; p < 3; p++) {
            const float* src = WdecS + (size_t)(half * 256 + 8 * p + dr) * D_DATA + d0 + dc * 4;
            u32 dst = wregu + (p * 192 + dr * 24 + dc * 4) * 4;
            CP16(dst, src);
            CP_COMMIT();
        }

        // bias + relu + gate + tf32-round -> acts[e][slot]
        {
            int e = e0 + g;
            float bgA  = benc[(size_t)s * D_DICT + e];
            float bgA8 = benc[(size_t)s * D_DICT + e + 8];
            float bgB  = benc[(size_t)s * D_DICT + e + 16];
            float bgB8 = benc[(size_t)s * D_DICT + e + 24];
            #pragma unroll
            for (int nt = 0; nt < 4; nt++) {
                int sl = nt * 8 + 2 * t;
                float gt0 = gsf[base + sl], gt1 = gsf[base + sl + 1];
                acts[(e     ) * 40 + sl    ] = __uint_as_float(tf32r(fmaxf(c0[nt][0] + bgA , 0.f) * gt0));
                acts[(e     ) * 40 + sl + 1] = __uint_as_float(tf32r(fmaxf(c0[nt][1] + bgA , 0.f) * gt1));
                acts[(e +  8) * 40 + sl    ] = __uint_as_float(tf32r(fmaxf(c0[nt][2] + bgA8, 0.f) * gt0));
                acts[(e +  8) * 40 + sl + 1] = __uint_as_float(tf32r(fmaxf(c0[nt][3] + bgA8, 0.f) * gt1));
                acts[(e + 16) * 40 + sl    ] = __uint_as_float(tf32r(fmaxf(c1[nt][0] + bgB , 0.f) * gt0));
                acts[(e + 16) * 40 + sl + 1] = __uint_as_float(tf32r(fmaxf(c1[nt][1] + bgB , 0.f) * gt1));
                acts[(e + 24) * 40 + sl    ] = __uint_as_float(tf32r(fmaxf(c1[nt][2] + bgB8, 0.f) * gt0));
                acts[(e + 24) * 40 + sl + 1] = __uint_as_float(tf32r(fmaxf(c1[nt][3] + bgB8, 0.f) * gt1));
            }
        }
        __syncthreads();                        // acts visible to all warps

        // ---------------- Decode: C[128d x 32tok] ----------------
        {
            float c[4][4];
            #pragma unroll
            for (int nt = 0; nt < 4; nt++)
                #pragma unroll
                for (int q = 0; q < 4; q++) c[nt][q] = 0.0f;

            #pragma unroll 4
            for (int ks = 0; ks < 32; ks++) {
                CP_WAIT2();
                if (ks + 3 < 32) {
                    int p = ks + 3;
                    const float* src = WdecS + (size_t)(half * 256 + 8 * p + dr) * D_DATA + d0 + dc * 4;
                    u32 dst = wregu + (((p & 3) * 192 + dr * 24 + dc * 4)) * 4;
                    CP16(dst, src);
                }
                CP_COMMIT();
                __syncwarp();

                const float* S = wreg + (ks & 3) * 192;
                u32 a0 = tf32s(S[t * 24 + g    ]);
                u32 a1 = tf32s(S[t * 24 + g + 8]);
                u32 a2 = tf32s(S[(t + 4) * 24 + g    ]);
                u32 a3 = tf32s(S[(t + 4) * 24 + g + 8]);
                #pragma unroll
                for (int nt = 0; nt < 4; nt++) {
                    u32 b0 = __float_as_uint(acts[(half * 256 + 8 * ks + t    ) * 40 + nt * 8 + g]);
                    u32 b1 = __float_as_uint(acts[(half * 256 + 8 * ks + t + 4) * 40 + nt * 8 + g]);
                    mma_tf32(c[nt][0], c[nt][1], c[nt][2], c[nt][3],
                             a0, a1, a2, a3, b0, b1);
                }
            }
            // part[half][token-pair nt*4+t][d] = pk(tok even, tok odd)
            #pragma unroll
            for (int nt = 0; nt < 4; nt++) {
                part[half * 2048 + (nt * 4 + t) * 128 + d0 + g    ] = pk(c[nt][0], c[nt][1]);
                part[half * 2048 + (nt * 4 + t) * 128 + d0 + g + 8] = pk(c[nt][2], c[nt][3]);
            }
        }
        __syncthreads();

        // ---- Epilogue: reduce K-halves + b_dec, lock-free combine (proven) ----
        {
            int d  = tid & 127;
            int tl = tid >> 7;             // 0..3; token pairs tl+4q
            float bd = bdec[(size_t)s * D_DATA + d];
            float vv[8];
            #pragma unroll
            for (int q = 0; q < 4; q++) {
                int tp = tl + 4 * q;
                u64 sum = add2(part[tp * 128 + d], part[2048 + tp * 128 + d]);
                float lo, hi; upk(lo, hi, sum);
                vv[2 * q] = lo + bd; vv[2 * q + 1] = hi + bd;
            }

            if (tid < TB) sarr[tid] = (tid < mb) ? atomicAdd(&g_arr[prtok[base + tid]], 1) : 0;
            __syncthreads();

            // Phase 1: publish first-role rows (parity 0).
            #pragma unroll
            for (int q = 0; q < 4; q++) {
                #pragma unroll
                for (int r = 0; r < 2; r++) {
                    int j = 2 * (tl + 4 * q) + r;
                    if (j < mb && (sarr[j] & 1) == 0)
                        __stcg(&g_stage[(size_t)prtok[base + j] * D_DATA + d], vv[2 * q + r]);
                }
            }
            __syncthreads();

            if (tid < mb && (sarr[tid] & 1) == 0) {
                __threadfence();
                atomicAdd(&g_ready[prtok[base + tid]], 1);
            }
            // Phase 2: spin (publish-before-spin => no deadlock).
            if (tid < mb && (sarr[tid] & 1) == 1) {
                int b = prtok[base + tid];
                int want = (sarr[tid] >> 1) + 1;
                while (atomicAdd(&g_ready[b], 0) < want) {}
                __threadfence();
            }
            __syncthreads();

            // Phase 3: combine and write final output (second-role tokens).
            #pragma unroll
            for (int q = 0; q < 4; q++) {
                #pragma unroll
                for (int r = 0; r < 2; r++) {
                    int j = 2 * (tl + 4 * q) + r;
                    if (j < mb && (sarr[j] & 1) == 1) {
                        int b = prtok[base + j];
                        float other = __ldcg(&g_stage[(size_t)b * D_DATA + d]);
                        out[(size_t)b * D_DATA + d] = vv[2 * q + r] + other;
                    }
                }
            }
        }
        __syncthreads();   // before next batch reuses wstg/xs/acts/part
    }
}

// ---------------------------------------------------------------------------
// Launch. Inputs (metadata order): x, gate, W_enc, W_dec, b_enc, b_dec, k
// ---------------------------------------------------------------------------
extern "C" void kernel_launch(void* const* d_in, const int* in_sizes, int n_in,
                              void* d_out, int out_size) {
    const float* x    = (const float*)d_in[0];
    const float* gate = (const float*)d_in[1];
    const float* Wenc = (const float*)d_in[2];
    const float* Wdec = (const float*)d_in[3];
    const float* benc = (const float*)d_in[4];
    const float* bdec = (const float*)d_in[5];
    float* out = (float*)d_out;

    cudaFuncSetAttribute(k_compute, cudaFuncAttributeMaxDynamicSharedMemorySize,
                         SMEM_BYTES);

    k_compute<<<N_SAE, 512, SMEM_BYTES>>>(x, gate, Wenc, Wdec, benc, bdec, out);
}